// round 1
// baseline (speedup 1.0000x reference)
#include <cuda_runtime.h>
#include <math.h>

#define HW    16384
#define IMW   128
#define IMH   128
#define CC    192
#define NB    8
#define NHEADS 8
#define HD    24
#define CHG   8   // gram hw-chunks

// ---------------- scratch (static device allocations are sanctioned) -------
__device__ float g_kv1[(size_t)NB*2*CC*HW];   // 1x1 kv output
__device__ float g_kv [(size_t)NB*2*CC*HW];   // after depthwise: k = [0..192), v = [192..384)
__device__ float g_q  [(size_t)NB*CC*HW];     // fused q conv output
__device__ float g_W2 [9*CC*CC];              // fused conv weights, layout [t][i][o]
__device__ float g_kvwT[CC*2*CC];             // kv_w transposed [i][o]
__device__ float g_Sp [(size_t)NB*NHEADS*CHG*HD*HD];
__device__ float g_nqp[(size_t)NB*NHEADS*CHG*HD];
__device__ float g_nkp[(size_t)NB*NHEADS*CHG*HD];
__device__ float g_Mt [(size_t)NB*CC*CC];     // per-batch fused proj*attn, layout [i][o]

// ---------------- tiny prep kernels ---------------------------------------
__global__ void transpose_kvw(const float* __restrict__ w, float* __restrict__ wt) {
    int l = blockIdx.x * blockDim.x + threadIdx.x;
    if (l < 2 * CC * CC) {
        int o = l / CC, i = l % CC;
        wt[i * (2 * CC) + o] = w[l];
    }
}

// W2[t][i][o] = sum_m qdw[o][m][t] * qw[m][i]
__global__ void build_w2(const float* __restrict__ qdw, const float* __restrict__ qw,
                         float* __restrict__ w2) {
    int o = blockIdx.x, t = blockIdx.y, i = threadIdx.x;
    __shared__ float dw[CC];
    dw[i] = qdw[(o * CC + i) * 9 + t];
    __syncthreads();
    float acc = 0.f;
    #pragma unroll 4
    for (int m = 0; m < CC; m++) acc += dw[m] * qw[m * CC + i];
    w2[(t * CC + i) * CC + o] = acc;
}

// ---------------- 1x1-conv GEMM: C[o,p] = sum_i A[i][o] * B[i,p] ----------
// A k-major [192][M]; B rows stride HW; 64x128 tile, 8x8 micro, 128 threads.
__global__ __launch_bounds__(128, 4)
void gemm1x1(const float* __restrict__ A, const float* __restrict__ B,
             float* __restrict__ C, int M,
             long aStride, long bStride, long cStride) {
    const int b = blockIdx.z;
    A += (long)b * aStride;
    B += (long)b * bStride;
    C += (long)b * cStride;
    const int p0 = blockIdx.x * 128, o0 = blockIdx.y * 64;

    __shared__ float As[16][64];
    __shared__ float Bs[16][128];

    const int tid = threadIdx.x;
    const int tx = tid & 15, ty = tid >> 4;

    float acc[8][8];
    #pragma unroll
    for (int m = 0; m < 8; m++)
        #pragma unroll
        for (int n = 0; n < 8; n++) acc[m][n] = 0.f;

    for (int i0 = 0; i0 < CC; i0 += 16) {
        #pragma unroll
        for (int r = 0; r < 2; r++) {
            int l = tid * 4 + r * 512;
            int ai = l >> 6, ao = l & 63;
            *(float4*)&As[ai][ao] = *(const float4*)(A + (long)(i0 + ai) * M + o0 + ao);
        }
        #pragma unroll
        for (int r = 0; r < 4; r++) {
            int l = tid * 4 + r * 512;
            int bi = l >> 7, bp = l & 127;
            *(float4*)&Bs[bi][bp] = *(const float4*)(B + (long)(i0 + bi) * HW + p0 + bp);
        }
        __syncthreads();
        #pragma unroll
        for (int k = 0; k < 16; k++) {
            float a[8], bb[8];
            *(float4*)&a[0]  = *(float4*)&As[k][ty * 8];
            *(float4*)&a[4]  = *(float4*)&As[k][ty * 8 + 4];
            *(float4*)&bb[0] = *(float4*)&Bs[k][tx * 8];
            *(float4*)&bb[4] = *(float4*)&Bs[k][tx * 8 + 4];
            #pragma unroll
            for (int m = 0; m < 8; m++)
                #pragma unroll
                for (int n = 0; n < 8; n++) acc[m][n] = fmaf(a[m], bb[n], acc[m][n]);
        }
        __syncthreads();
    }
    #pragma unroll
    for (int m = 0; m < 8; m++) {
        float* cp = C + (long)(o0 + ty * 8 + m) * HW + p0 + tx * 8;
        float4 v0 = make_float4(acc[m][0], acc[m][1], acc[m][2], acc[m][3]);
        float4 v1 = make_float4(acc[m][4], acc[m][5], acc[m][6], acc[m][7]);
        *(float4*)cp = v0;
        *(float4*)(cp + 4) = v1;
    }
}

// ---------------- fused q conv: implicit GEMM over 9 taps × 192 ch --------
// N-tile = one full image row (128 px), so tap shifts are simple row/col masks.
__global__ __launch_bounds__(128, 4)
void conv3x3(const float* __restrict__ W2, const float* __restrict__ Y,
             float* __restrict__ Q) {
    const int b = blockIdx.z, py = blockIdx.x, o0 = blockIdx.y * 64;
    const float* Yb = Y + (long)b * CC * HW;

    __shared__ float As[16][64];
    __shared__ float Bs[16][128];

    const int tid = threadIdx.x;
    const int tx = tid & 15, ty = tid >> 4;

    float acc[8][8];
    #pragma unroll
    for (int m = 0; m < 8; m++)
        #pragma unroll
        for (int n = 0; n < 8; n++) acc[m][n] = 0.f;

    for (int t = 0; t < 9; t++) {
        const int dy = t / 3 - 1, dx = t % 3 - 1;
        const int iy = py + dy;
        if (iy < 0 || iy >= IMH) continue;         // uniform across block
        const float* Yrow = Yb + (long)iy * IMW;
        const float* Wt   = W2 + (long)t * CC * CC;

        for (int i0 = 0; i0 < CC; i0 += 16) {
            #pragma unroll
            for (int r = 0; r < 2; r++) {
                int l = tid * 4 + r * 512;
                int ai = l >> 6, ao = l & 63;
                *(float4*)&As[ai][ao] = *(const float4*)(Wt + (long)(i0 + ai) * CC + o0 + ao);
            }
            #pragma unroll
            for (int r = 0; r < 16; r++) {
                int px = tid + dx;
                Bs[r][tid] = (px >= 0 && px < IMW)
                             ? Yrow[(long)(i0 + r) * HW + px] : 0.f;
            }
            __syncthreads();
            #pragma unroll
            for (int k = 0; k < 16; k++) {
                float a[8], bb[8];
                *(float4*)&a[0]  = *(float4*)&As[k][ty * 8];
                *(float4*)&a[4]  = *(float4*)&As[k][ty * 8 + 4];
                *(float4*)&bb[0] = *(float4*)&Bs[k][tx * 8];
                *(float4*)&bb[4] = *(float4*)&Bs[k][tx * 8 + 4];
                #pragma unroll
                for (int m = 0; m < 8; m++)
                    #pragma unroll
                    for (int n = 0; n < 8; n++) acc[m][n] = fmaf(a[m], bb[n], acc[m][n]);
            }
            __syncthreads();
        }
    }
    const int p0 = py * IMW;
    #pragma unroll
    for (int m = 0; m < 8; m++) {
        float* cp = Q + ((long)b * CC + o0 + ty * 8 + m) * HW + p0 + tx * 8;
        float4 v0 = make_float4(acc[m][0], acc[m][1], acc[m][2], acc[m][3]);
        float4 v1 = make_float4(acc[m][4], acc[m][5], acc[m][6], acc[m][7]);
        *(float4*)cp = v0;
        *(float4*)(cp + 4) = v1;
    }
}

// ---------------- depthwise 3x3, SAME -------------------------------------
__global__ void dwconv(const float* __restrict__ in, const float* __restrict__ w,
                       float* __restrict__ out) {
    long n = (long)blockIdx.x * blockDim.x + threadIdx.x;
    if (n >= (long)NB * 2 * CC * HW) return;
    const int px = (int)(n & 127);
    const int py = (int)((n >> 7) & 127);
    const int ch = (int)((n >> 14) % (2 * CC));
    const float* base = in + ((n >> 14) << 14);
    float acc = 0.f;
    #pragma unroll
    for (int t = 0; t < 9; t++) {
        int dy = t / 3 - 1, dx = t % 3 - 1;
        int iy = py + dy, ix = px + dx;
        if (iy >= 0 && iy < IMH && ix >= 0 && ix < IMW)
            acc += w[ch * 9 + t] * base[iy * IMW + ix];
    }
    out[n] = acc;
}

// ---------------- gram + norms per (b, head, chunk) -----------------------
__global__ void gram(const float* __restrict__ q, const float* __restrict__ k,
                     float* __restrict__ Sp, float* __restrict__ nqp,
                     float* __restrict__ nkp) {
    const int ch = blockIdx.x, h = blockIdx.y, b = blockIdx.z;
    const int tid = threadIdx.x;               // 576
    const int c = tid / HD, d = tid % HD;
    __shared__ float sq[128][HD + 1];
    __shared__ float sk[128][HD + 1];
    const float* qb = q + ((long)b * CC + h * HD) * HW;
    const float* kb = k + ((long)b * 2 * CC + h * HD) * HW;   // k = first 192 ch of g_kv

    float acc = 0.f, aq = 0.f, ak = 0.f;
    const int e_begin = ch * (HW / CHG), e_end = e_begin + HW / CHG;
    for (int e0 = e_begin; e0 < e_end; e0 += 128) {
        __syncthreads();
        for (int l = tid; l < HD * 128; l += 576) {
            int r = l >> 7, e = l & 127;
            sq[e][r] = qb[(long)r * HW + e0 + e];
            sk[e][r] = kb[(long)r * HW + e0 + e];
        }
        __syncthreads();
        #pragma unroll 8
        for (int e = 0; e < 128; e++) {
            float qa = sq[e][c], kv = sk[e][d];
            acc = fmaf(qa, kv, acc);
            if (c == d) { aq = fmaf(qa, qa, aq); ak = fmaf(kv, kv, ak); }
        }
    }
    long base = ((long)b * NHEADS + h) * CHG + ch;
    Sp[base * (HD * HD) + tid] = acc;
    if (c == d) { nqp[base * HD + c] = aq; nkp[base * HD + c] = ak; }
}

// ---------------- softmax + M = proj * blockdiag(attn), stored [i][o] -----
__global__ void attn_m(const float* __restrict__ Sp, const float* __restrict__ nqp,
                       const float* __restrict__ nkp, const float* __restrict__ temp,
                       const float* __restrict__ proj, float* __restrict__ Mt) {
    const int h = blockIdx.x, b = blockIdx.y, tid = threadIdx.x;  // 576 threads
    __shared__ float sA[HD][HD + 1];
    __shared__ float snq[HD], snk[HD];
    const long base = ((long)b * NHEADS + h) * CHG;

    float s = 0.f;
    for (int cc = 0; cc < CHG; cc++) s += Sp[(base + cc) * (HD * HD) + tid];

    if (tid < HD) {
        float a = 0.f, kk = 0.f;
        for (int cc = 0; cc < CHG; cc++) {
            a  += nqp[(base + cc) * HD + tid];
            kk += nkp[(base + cc) * HD + tid];
        }
        snq[tid] = fmaxf(sqrtf(a),  1e-12f);
        snk[tid] = fmaxf(sqrtf(kk), 1e-12f);
    }
    __syncthreads();
    {
        int c = tid / HD, d = tid % HD;
        sA[c][d] = s / (snq[c] * snk[d]) * temp[h];
    }
    __syncthreads();
    if (tid < HD) {                           // softmax over d, row tid
        float mx = -1e30f;
        for (int d = 0; d < HD; d++) mx = fmaxf(mx, sA[tid][d]);
        float sum = 0.f;
        for (int d = 0; d < HD; d++) { float e = expf(sA[tid][d] - mx); sA[tid][d] = e; sum += e; }
        float inv = 1.f / sum;
        for (int d = 0; d < HD; d++) sA[tid][d] *= inv;
    }
    __syncthreads();
    for (int l = tid; l < HD * CC; l += 576) {
        int d = l / CC, o = l % CC;
        float acc = 0.f;
        #pragma unroll
        for (int c = 0; c < HD; c++) acc += proj[o * CC + h * HD + c] * sA[c][d];
        Mt[((long)b * CC + h * HD + d) * CC + o] = acc;
    }
}

// ---------------- launch ---------------------------------------------------
extern "C" void kernel_launch(void* const* d_in, const int* in_sizes, int n_in,
                              void* d_out, int out_size) {
    const float* x    = (const float*)d_in[0];
    const float* y    = (const float*)d_in[1];
    const float* temp = (const float*)d_in[2];
    const float* kvw  = (const float*)d_in[3];
    const float* kvdw = (const float*)d_in[4];
    const float* qw   = (const float*)d_in[5];
    const float* qdw  = (const float*)d_in[6];
    const float* proj = (const float*)d_in[7];
    float* out = (float*)d_out;

    float *kv1, *kv, *q, *w2, *kvwT, *Sp, *nqp, *nkp, *Mt;
    cudaGetSymbolAddress((void**)&kv1,  g_kv1);
    cudaGetSymbolAddress((void**)&kv,   g_kv);
    cudaGetSymbolAddress((void**)&q,    g_q);
    cudaGetSymbolAddress((void**)&w2,   g_W2);
    cudaGetSymbolAddress((void**)&kvwT, g_kvwT);
    cudaGetSymbolAddress((void**)&Sp,   g_Sp);
    cudaGetSymbolAddress((void**)&nqp,  g_nqp);
    cudaGetSymbolAddress((void**)&nkp,  g_nkp);
    cudaGetSymbolAddress((void**)&Mt,   g_Mt);

    transpose_kvw<<<(2 * CC * CC + 255) / 256, 256>>>(kvw, kvwT);
    build_w2<<<dim3(CC, 9), CC>>>(qdw, qw, w2);

    // kv = 1x1 conv (x)  : M = 384
    gemm1x1<<<dim3(128, 6, NB), 128>>>(kvwT, x, kv1, 2 * CC,
                                       0L, (long)CC * HW, (long)2 * CC * HW);
    // depthwise 3x3
    dwconv<<<(int)(((long)NB * 2 * CC * HW + 255) / 256), 256>>>(kv1, kvdw, kv);
    // q = fused 1x1 + dense 3x3 (y)
    conv3x3<<<dim3(128, 3, NB), 128>>>(w2, y, q);
    // gram + norms
    gram<<<dim3(CHG, NHEADS, NB), 576>>>(q, kv, Sp, nqp, nkp);
    // softmax + fused proj*attn matrices
    attn_m<<<dim3(NHEADS, NB), 576>>>(Sp, nqp, nkp, temp, proj, Mt);
    // out = M_b @ v_b  : M = 192, v = second half of kv
    gemm1x1<<<dim3(128, 3, NB), 128>>>(Mt, kv + (long)CC * HW, out, CC,
                                       (long)CC * CC, (long)2 * CC * HW, (long)CC * HW);
}

// round 2
// speedup vs baseline: 1.0012x; 1.0012x over previous
#include <cuda_runtime.h>
#include <math.h>

#define HW    16384
#define IMW   128
#define IMH   128
#define CC    192
#define NB    8
#define NHEADS 8
#define HD    24
#define CHG   8   // gram hw-chunks

// ---------------- scratch (static device allocations are sanctioned) -------
__device__ float g_kv1[(size_t)NB*2*CC*HW];   // 1x1 kv output
__device__ float g_kv [(size_t)NB*2*CC*HW];   // after depthwise: k = [0..192), v = [192..384)
__device__ float g_q  [(size_t)NB*CC*HW];     // fused q conv output
__device__ float g_W2 [9*CC*CC];              // fused conv weights, layout [t][i][o]
__device__ float g_kvwT[CC*2*CC];             // kv_w transposed [i][o]
__device__ float g_Sp [(size_t)NB*NHEADS*CHG*HD*HD];
__device__ float g_nqp[(size_t)NB*NHEADS*CHG*HD];
__device__ float g_nkp[(size_t)NB*NHEADS*CHG*HD];
__device__ float g_Mt [(size_t)NB*CC*CC];     // per-batch fused proj*attn, layout [i][o]

// ---------------- tiny prep kernels ---------------------------------------
__global__ void transpose_kvw(const float* __restrict__ w, float* __restrict__ wt) {
    int l = blockIdx.x * blockDim.x + threadIdx.x;
    if (l < 2 * CC * CC) {
        int o = l / CC, i = l % CC;
        wt[i * (2 * CC) + o] = w[l];
    }
}

// W2[t][i][o] = sum_m qdw[o][m][t] * qw[m][i]
__global__ void build_w2(const float* __restrict__ qdw, const float* __restrict__ qw,
                         float* __restrict__ w2) {
    int o = blockIdx.x, t = blockIdx.y, i = threadIdx.x;
    __shared__ float dw[CC];
    dw[i] = qdw[(o * CC + i) * 9 + t];
    __syncthreads();
    float acc = 0.f;
    #pragma unroll 4
    for (int m = 0; m < CC; m++) acc += dw[m] * qw[m * CC + i];
    w2[(t * CC + i) * CC + o] = acc;
}

// ---------------- 1x1-conv GEMM: C[o,p] = sum_i A[i][o] * B[i,p] ----------
// A k-major [192][M]; B rows stride HW; 64x128 tile, 8x8 micro, 128 threads.
__global__ __launch_bounds__(128, 4)
void gemm1x1(const float* __restrict__ A, const float* __restrict__ B,
             float* __restrict__ C, int M,
             long aStride, long bStride, long cStride) {
    const int b = blockIdx.z;
    A += (long)b * aStride;
    B += (long)b * bStride;
    C += (long)b * cStride;
    const int p0 = blockIdx.x * 128, o0 = blockIdx.y * 64;

    __shared__ float As[16][64];
    __shared__ float Bs[16][128];

    const int tid = threadIdx.x;
    const int tx = tid & 15, ty = tid >> 4;

    float acc[8][8];
    #pragma unroll
    for (int m = 0; m < 8; m++)
        #pragma unroll
        for (int n = 0; n < 8; n++) acc[m][n] = 0.f;

    for (int i0 = 0; i0 < CC; i0 += 16) {
        #pragma unroll
        for (int r = 0; r < 2; r++) {
            int l = tid * 4 + r * 512;
            int ai = l >> 6, ao = l & 63;
            *(float4*)&As[ai][ao] = *(const float4*)(A + (long)(i0 + ai) * M + o0 + ao);
        }
        #pragma unroll
        for (int r = 0; r < 4; r++) {
            int l = tid * 4 + r * 512;
            int bi = l >> 7, bp = l & 127;
            *(float4*)&Bs[bi][bp] = *(const float4*)(B + (long)(i0 + bi) * HW + p0 + bp);
        }
        __syncthreads();
        #pragma unroll
        for (int k = 0; k < 16; k++) {
            float a[8], bb[8];
            *(float4*)&a[0]  = *(float4*)&As[k][ty * 8];
            *(float4*)&a[4]  = *(float4*)&As[k][ty * 8 + 4];
            *(float4*)&bb[0] = *(float4*)&Bs[k][tx * 8];
            *(float4*)&bb[4] = *(float4*)&Bs[k][tx * 8 + 4];
            #pragma unroll
            for (int m = 0; m < 8; m++)
                #pragma unroll
                for (int n = 0; n < 8; n++) acc[m][n] = fmaf(a[m], bb[n], acc[m][n]);
        }
        __syncthreads();
    }
    #pragma unroll
    for (int m = 0; m < 8; m++) {
        float* cp = C + (long)(o0 + ty * 8 + m) * HW + p0 + tx * 8;
        float4 v0 = make_float4(acc[m][0], acc[m][1], acc[m][2], acc[m][3]);
        float4 v1 = make_float4(acc[m][4], acc[m][5], acc[m][6], acc[m][7]);
        *(float4*)cp = v0;
        *(float4*)(cp + 4) = v1;
    }
}

// ---------------- fused q conv: implicit GEMM over 9 taps × 192 ch --------
// N-tile = one full image row (128 px), so tap shifts are simple row/col masks.
__global__ __launch_bounds__(128, 4)
void conv3x3(const float* __restrict__ W2, const float* __restrict__ Y,
             float* __restrict__ Q) {
    const int b = blockIdx.z, py = blockIdx.x, o0 = blockIdx.y * 64;
    const float* Yb = Y + (long)b * CC * HW;

    __shared__ float As[16][64];
    __shared__ float Bs[16][128];

    const int tid = threadIdx.x;
    const int tx = tid & 15, ty = tid >> 4;

    float acc[8][8];
    #pragma unroll
    for (int m = 0; m < 8; m++)
        #pragma unroll
        for (int n = 0; n < 8; n++) acc[m][n] = 0.f;

    for (int t = 0; t < 9; t++) {
        const int dy = t / 3 - 1, dx = t % 3 - 1;
        const int iy = py + dy;
        if (iy < 0 || iy >= IMH) continue;         // uniform across block
        const float* Yrow = Yb + (long)iy * IMW;
        const float* Wt   = W2 + (long)t * CC * CC;

        for (int i0 = 0; i0 < CC; i0 += 16) {
            #pragma unroll
            for (int r = 0; r < 2; r++) {
                int l = tid * 4 + r * 512;
                int ai = l >> 6, ao = l & 63;
                *(float4*)&As[ai][ao] = *(const float4*)(Wt + (long)(i0 + ai) * CC + o0 + ao);
            }
            #pragma unroll
            for (int r = 0; r < 16; r++) {
                int px = tid + dx;
                Bs[r][tid] = (px >= 0 && px < IMW)
                             ? Yrow[(long)(i0 + r) * HW + px] : 0.f;
            }
            __syncthreads();
            #pragma unroll
            for (int k = 0; k < 16; k++) {
                float a[8], bb[8];
                *(float4*)&a[0]  = *(float4*)&As[k][ty * 8];
                *(float4*)&a[4]  = *(float4*)&As[k][ty * 8 + 4];
                *(float4*)&bb[0] = *(float4*)&Bs[k][tx * 8];
                *(float4*)&bb[4] = *(float4*)&Bs[k][tx * 8 + 4];
                #pragma unroll
                for (int m = 0; m < 8; m++)
                    #pragma unroll
                    for (int n = 0; n < 8; n++) acc[m][n] = fmaf(a[m], bb[n], acc[m][n]);
            }
            __syncthreads();
        }
    }
    const int p0 = py * IMW;
    #pragma unroll
    for (int m = 0; m < 8; m++) {
        float* cp = Q + ((long)b * CC + o0 + ty * 8 + m) * HW + p0 + tx * 8;
        float4 v0 = make_float4(acc[m][0], acc[m][1], acc[m][2], acc[m][3]);
        float4 v1 = make_float4(acc[m][4], acc[m][5], acc[m][6], acc[m][7]);
        *(float4*)cp = v0;
        *(float4*)(cp + 4) = v1;
    }
}

// ---------------- depthwise 3x3, SAME -------------------------------------
__global__ void dwconv(const float* __restrict__ in, const float* __restrict__ w,
                       float* __restrict__ out) {
    long n = (long)blockIdx.x * blockDim.x + threadIdx.x;
    if (n >= (long)NB * 2 * CC * HW) return;
    const int px = (int)(n & 127);
    const int py = (int)((n >> 7) & 127);
    const int ch = (int)((n >> 14) % (2 * CC));
    const float* base = in + ((n >> 14) << 14);
    float acc = 0.f;
    #pragma unroll
    for (int t = 0; t < 9; t++) {
        int dy = t / 3 - 1, dx = t % 3 - 1;
        int iy = py + dy, ix = px + dx;
        if (iy >= 0 && iy < IMH && ix >= 0 && ix < IMW)
            acc += w[ch * 9 + t] * base[iy * IMW + ix];
    }
    out[n] = acc;
}

// ---------------- gram + norms per (b, head, chunk) -----------------------
__global__ void gram(const float* __restrict__ q, const float* __restrict__ k,
                     float* __restrict__ Sp, float* __restrict__ nqp,
                     float* __restrict__ nkp) {
    const int ch = blockIdx.x, h = blockIdx.y, b = blockIdx.z;
    const int tid = threadIdx.x;               // 576
    const int c = tid / HD, d = tid % HD;
    __shared__ float sq[128][HD + 1];
    __shared__ float sk[128][HD + 1];
    const float* qb = q + ((long)b * CC + h * HD) * HW;
    const float* kb = k + ((long)b * 2 * CC + h * HD) * HW;   // k = first 192 ch of g_kv

    float acc = 0.f, aq = 0.f, ak = 0.f;
    const int e_begin = ch * (HW / CHG), e_end = e_begin + HW / CHG;
    for (int e0 = e_begin; e0 < e_end; e0 += 128) {
        __syncthreads();
        for (int l = tid; l < HD * 128; l += 576) {
            int r = l >> 7, e = l & 127;
            sq[e][r] = qb[(long)r * HW + e0 + e];
            sk[e][r] = kb[(long)r * HW + e0 + e];
        }
        __syncthreads();
        #pragma unroll 8
        for (int e = 0; e < 128; e++) {
            float qa = sq[e][c], kv = sk[e][d];
            acc = fmaf(qa, kv, acc);
            if (c == d) { aq = fmaf(qa, qa, aq); ak = fmaf(kv, kv, ak); }
        }
    }
    long base = ((long)b * NHEADS + h) * CHG + ch;
    Sp[base * (HD * HD) + tid] = acc;
    if (c == d) { nqp[base * HD + c] = aq; nkp[base * HD + c] = ak; }
}

// ---------------- softmax + M = proj * blockdiag(attn), stored [i][o] -----
__global__ void attn_m(const float* __restrict__ Sp, const float* __restrict__ nqp,
                       const float* __restrict__ nkp, const float* __restrict__ temp,
                       const float* __restrict__ proj, float* __restrict__ Mt) {
    const int h = blockIdx.x, b = blockIdx.y, tid = threadIdx.x;  // 576 threads
    __shared__ float sA[HD][HD + 1];
    __shared__ float snq[HD], snk[HD];
    const long base = ((long)b * NHEADS + h) * CHG;

    float s = 0.f;
    for (int cc = 0; cc < CHG; cc++) s += Sp[(base + cc) * (HD * HD) + tid];

    if (tid < HD) {
        float a = 0.f, kk = 0.f;
        for (int cc = 0; cc < CHG; cc++) {
            a  += nqp[(base + cc) * HD + tid];
            kk += nkp[(base + cc) * HD + tid];
        }
        snq[tid] = fmaxf(sqrtf(a),  1e-12f);
        snk[tid] = fmaxf(sqrtf(kk), 1e-12f);
    }
    __syncthreads();
    {
        int c = tid / HD, d = tid % HD;
        sA[c][d] = s / (snq[c] * snk[d]) * temp[h];
    }
    __syncthreads();
    if (tid < HD) {                           // softmax over d, row tid
        float mx = -1e30f;
        for (int d = 0; d < HD; d++) mx = fmaxf(mx, sA[tid][d]);
        float sum = 0.f;
        for (int d = 0; d < HD; d++) { float e = expf(sA[tid][d] - mx); sA[tid][d] = e; sum += e; }
        float inv = 1.f / sum;
        for (int d = 0; d < HD; d++) sA[tid][d] *= inv;
    }
    __syncthreads();
    for (int l = tid; l < HD * CC; l += 576) {
        int d = l / CC, o = l % CC;
        float acc = 0.f;
        #pragma unroll
        for (int c = 0; c < HD; c++) acc += proj[o * CC + h * HD + c] * sA[c][d];
        Mt[((long)b * CC + h * HD + d) * CC + o] = acc;
    }
}

// ---------------- launch ---------------------------------------------------
extern "C" void kernel_launch(void* const* d_in, const int* in_sizes, int n_in,
                              void* d_out, int out_size) {
    const float* x    = (const float*)d_in[0];
    const float* y    = (const float*)d_in[1];
    const float* temp = (const float*)d_in[2];
    const float* kvw  = (const float*)d_in[3];
    const float* kvdw = (const float*)d_in[4];
    const float* qw   = (const float*)d_in[5];
    const float* qdw  = (const float*)d_in[6];
    const float* proj = (const float*)d_in[7];
    float* out = (float*)d_out;

    float *kv1, *kv, *q, *w2, *kvwT, *Sp, *nqp, *nkp, *Mt;
    cudaGetSymbolAddress((void**)&kv1,  g_kv1);
    cudaGetSymbolAddress((void**)&kv,   g_kv);
    cudaGetSymbolAddress((void**)&q,    g_q);
    cudaGetSymbolAddress((void**)&w2,   g_W2);
    cudaGetSymbolAddress((void**)&kvwT, g_kvwT);
    cudaGetSymbolAddress((void**)&Sp,   g_Sp);
    cudaGetSymbolAddress((void**)&nqp,  g_nqp);
    cudaGetSymbolAddress((void**)&nkp,  g_nkp);
    cudaGetSymbolAddress((void**)&Mt,   g_Mt);

    transpose_kvw<<<(2 * CC * CC + 255) / 256, 256>>>(kvw, kvwT);
    build_w2<<<dim3(CC, 9), CC>>>(qdw, qw, w2);

    // kv = 1x1 conv (x)  : M = 384
    gemm1x1<<<dim3(128, 6, NB), 128>>>(kvwT, x, kv1, 2 * CC,
                                       0L, (long)CC * HW, (long)2 * CC * HW);
    // depthwise 3x3
    dwconv<<<(int)(((long)NB * 2 * CC * HW + 255) / 256), 256>>>(kv1, kvdw, kv);
    // q = fused 1x1 + dense 3x3 (y)
    conv3x3<<<dim3(128, 3, NB), 128>>>(w2, y, q);
    // gram + norms
    gram<<<dim3(CHG, NHEADS, NB), 576>>>(q, kv, Sp, nqp, nkp);
    // softmax + fused proj*attn matrices
    attn_m<<<dim3(NHEADS, NB), 576>>>(Sp, nqp, nkp, temp, proj, Mt);
    // out = M_b @ v_b  : M = 192, v = second half of kv
    gemm1x1<<<dim3(128, 3, NB), 128>>>(Mt, kv + (long)CC * HW, out, CC,
                                       (long)CC * CC, (long)2 * CC * HW, (long)CC * HW);
}

// round 4
// speedup vs baseline: 2.6013x; 2.5982x over previous
#include <cuda_runtime.h>
#include <cuda_fp16.h>
#include <math.h>
#include <stdint.h>

#define HW    16384
#define IMW   128
#define IMH   128
#define CC    192
#define NB    8
#define NHEADS 8
#define HD    24
#define CHG   8
#define KQ    (9*CC)           // 1728
#define PADW  130
#define PADHW (IMH*PADW)       // 16640
#define YSLOTS (PADHW + 2*PADW) // guard row top+bottom

// ---------------- scratch ---------------------------------------------------
__device__ __align__(1024) __half g_xH  [(size_t)NB*HW*CC];
__device__ __align__(1024) __half g_yTpH[(size_t)NB*YSLOTS*CC];
__device__ __align__(1024) __half g_vH  [(size_t)NB*HW*CC];
__device__ __align__(1024) __half g_w2H [(size_t)CC*KQ];      // [o][t*192+i]
__device__ __align__(1024) __half g_kvwH[2*CC*CC];            // [o][i]
__device__ __align__(1024) __half g_MoH [(size_t)NB*CC*CC];   // [b][o][i]
__device__ __align__(1024) float  g_kv1[(size_t)NB*2*CC*HW];
__device__ __align__(1024) float  g_kv [(size_t)NB*2*CC*HW];
__device__ __align__(1024) float  g_q  [(size_t)NB*CC*HW];
__device__ float g_Sp [(size_t)NB*NHEADS*CHG*HD*HD];
__device__ float g_nqp[(size_t)NB*NHEADS*CHG*HD];
__device__ float g_nkp[(size_t)NB*NHEADS*CHG*HD];

__device__ __forceinline__ uint32_t smem_u32(const void* p) {
    uint32_t a;
    asm("{ .reg .u64 t; cvta.to.shared.u64 t, %1; cvt.u32.u64 %0, t; }"
        : "=r"(a) : "l"(p));
    return a;
}

#define LDSM_X4(r0, r1, r2, r3, addr) \
    asm volatile("ldmatrix.sync.aligned.m8n8.x4.shared.b16 {%0,%1,%2,%3}, [%4];" \
                 : "=r"(r0), "=r"(r1), "=r"(r2), "=r"(r3) : "r"(addr))

#define MMA16816(d, a, b0v, b1v) \
    asm volatile("mma.sync.aligned.m16n8k16.row.col.f32.f16.f16.f32 " \
                 "{%0,%1,%2,%3}, {%4,%5,%6,%7}, {%8,%9}, {%0,%1,%2,%3};" \
                 : "+f"((d)[0]), "+f"((d)[1]), "+f"((d)[2]), "+f"((d)[3]) \
                 : "r"((a)[0]), "r"((a)[1]), "r"((a)[2]), "r"((a)[3]), \
                   "r"(b0v), "r"(b1v))

#define CP16(dst, src) \
    asm volatile("cp.async.cg.shared.global [%0], [%1], 16;" \
                 :: "r"(dst), "l"(src))

// ---------------- fp16 mma GEMM --------------------------------------------
// C[o][p] (fp32, channel-major) = sum_k A[p][k] * B[o][k]
// block: 256 thr, tile 128(p) x 192(o), BK=32, cp.async double buffer.
// conv_mode: A = padded y layout, chunk c -> tap t=c/6 (row shift), ch (c%6)*32.
#define SM_STAGE 25600      // A 128*40*2 = 10240  +  B 192*40*2 = 15360
#define SM_TOTAL (2*SM_STAGE)

__device__ __forceinline__ void stage_load(
    uint32_t sb, int s, const __half* __restrict__ Ag,
    const __half* __restrict__ Bg, int c, int conv_mode, int KB, int o0, int tid)
{
    int t  = c / 6;
    int i0 = (c - t * 6) * 32;
    long arow;
    if (conv_mode) {
        int dy = t / 3 - 1, dx = t - t / 3 * 3 - 1;
        arow = (long)(blockIdx.x + dy + 1) * PADW + 1 + dx;
    } else {
        arow = (long)blockIdx.x * 128;
    }
    uint32_t sA = sb + s * SM_STAGE;
    uint32_t sB = sA + 10240;
    #pragma unroll
    for (int it = 0; it < 2; it++) {
        int ck = tid + it * 256;            // 512 chunks of 16B
        int r = ck >> 2, off = ck & 3;
        uint64_t src = __cvta_generic_to_global(Ag + (arow + r) * (long)CC + i0 + off * 8);
        CP16(sA + r * 80 + off * 16, src);
    }
    #pragma unroll
    for (int it = 0; it < 3; it++) {
        int ck = tid + it * 256;            // 768 chunks
        int r = ck >> 2, off = ck & 3;
        uint64_t src = __cvta_generic_to_global(Bg + (long)(o0 + r) * KB + c * 32 + off * 8);
        CP16(sB + r * 80 + off * 16, src);
    }
    asm volatile("cp.async.commit_group;");
}

__global__ __launch_bounds__(256)
void gemm_h(const __half* __restrict__ A, const __half* __restrict__ B,
            float* __restrict__ C, long aBatch, long bBatch, long cBatch,
            int KB, int nc, int conv_mode)
{
    extern __shared__ __align__(128) char sm[];
    const uint32_t sb = smem_u32(sm);
    const int tid = threadIdx.x, lane = tid & 31, wid = tid >> 5;
    const int wp = wid & 1, wo = wid >> 1;          // p-half, o-quarter
    const int b = blockIdx.z, o0 = blockIdx.y * 192;
    const __half* Ag = A + (long)b * aBatch;
    const __half* Bg = B + (long)b * bBatch;
    float* Cb = C + (long)b * cBatch;

    float acc[4][6][4];
    #pragma unroll
    for (int mf = 0; mf < 4; mf++)
        #pragma unroll
        for (int nf = 0; nf < 6; nf++)
            #pragma unroll
            for (int r = 0; r < 4; r++) acc[mf][nf][r] = 0.f;

    stage_load(sb, 0, Ag, Bg, 0, conv_mode, KB, o0, tid);

    const int t8 = lane >> 3, r8 = lane & 7;
    const int am = (t8 & 1) * 8 + r8, ak = (t8 >> 1) * 8;  // A supply coords
    const int bn = (t8 >> 1) * 8 + r8, bk = (t8 & 1) * 8;  // B supply coords

    for (int c = 0; c < nc; c++) {
        if (c + 1 < nc) {
            stage_load(sb, (c + 1) & 1, Ag, Bg, c + 1, conv_mode, KB, o0, tid);
            asm volatile("cp.async.wait_group 1;");
        } else {
            asm volatile("cp.async.wait_group 0;");
        }
        __syncthreads();
        uint32_t sA = sb + (c & 1) * SM_STAGE;
        uint32_t sB = sA + 10240;
        #pragma unroll
        for (int ks = 0; ks < 2; ks++) {
            uint32_t a[4][4], bf[3][4];
            #pragma unroll
            for (int mf = 0; mf < 4; mf++) {
                uint32_t addr = sA + (uint32_t)(((wp * 64 + mf * 16 + am) * 40 + ks * 16 + ak) * 2);
                LDSM_X4(a[mf][0], a[mf][1], a[mf][2], a[mf][3], addr);
            }
            #pragma unroll
            for (int pp = 0; pp < 3; pp++) {
                uint32_t addr = sB + (uint32_t)(((wo * 48 + pp * 16 + bn) * 40 + ks * 16 + bk) * 2);
                LDSM_X4(bf[pp][0], bf[pp][1], bf[pp][2], bf[pp][3], addr);
            }
            #pragma unroll
            for (int mf = 0; mf < 4; mf++)
                #pragma unroll
                for (int nf = 0; nf < 6; nf++)
                    MMA16816(acc[mf][nf], a[mf], bf[nf >> 1][(nf & 1) * 2],
                             bf[nf >> 1][(nf & 1) * 2 + 1]);
        }
        __syncthreads();
    }

    const int prow = blockIdx.x * 128 + wp * 64 + (lane >> 2);
    const int ocol = o0 + wo * 48 + (lane & 3) * 2;
    #pragma unroll
    for (int mf = 0; mf < 4; mf++)
        #pragma unroll
        for (int nf = 0; nf < 6; nf++) {
            int p = prow + mf * 16;
            int o = ocol + nf * 8;
            Cb[(long)o * HW + p]         = acc[mf][nf][0];
            Cb[(long)(o + 1) * HW + p]   = acc[mf][nf][1];
            Cb[(long)o * HW + p + 8]     = acc[mf][nf][2];
            Cb[(long)(o + 1) * HW + p + 8] = acc[mf][nf][3];
        }
}

// ---------------- producers -------------------------------------------------
__global__ void conv_h(const float* __restrict__ in, __half* __restrict__ out, int n) {
    int i = blockIdx.x * 256 + threadIdx.x;
    if (i < n) out[i] = __float2half(in[i]);
}

// w2H[o][t*192+i] = half( sum_m qdw[o][m][t] * qw[m][i] )
__global__ void build_w2h(const float* __restrict__ qdw, const float* __restrict__ qw,
                          __half* __restrict__ w2h) {
    int o = blockIdx.x, t = blockIdx.y, i = threadIdx.x;
    __shared__ float dw[CC];
    dw[i] = qdw[(o * CC + i) * 9 + t];
    __syncthreads();
    float acc = 0.f;
    #pragma unroll 4
    for (int m = 0; m < CC; m++) acc += dw[m] * qw[m * CC + i];
    w2h[(long)o * KQ + t * CC + i] = __float2half(acc);
}

// [b][c][hw] fp32 -> [b][slot][c] half; pad=1 -> 130-wide padded rows
__global__ void transpose_h(const float* __restrict__ in, long inB,
                            __half* __restrict__ out, long outB, int pad)
{
    __shared__ float t[32][33];
    int b = blockIdx.z, px0 = blockIdx.x * 32, c0 = blockIdx.y * 32;
    int tx = threadIdx.x, ty = threadIdx.y;
    const float* ib = in + (long)b * inB;
    #pragma unroll
    for (int j = 0; j < 4; j++)
        t[ty + j * 8][tx] = ib[(long)(c0 + ty + j * 8) * HW + px0 + tx];
    __syncthreads();
    __half* ob = out + (long)b * outB;
    #pragma unroll
    for (int j = 0; j < 4; j++) {
        int px = px0 + ty + j * 8;
        long slot = pad ? (long)(px >> 7) * PADW + 1 + (px & 127) : px;
        ob[slot * CC + c0 + tx] = __float2half(t[tx][ty + j * 8]);
    }
}

// ---------------- depthwise 3x3, SAME --------------------------------------
__global__ void dwconv(const float* __restrict__ in, const float* __restrict__ w,
                       float* __restrict__ out) {
    long n = (long)blockIdx.x * blockDim.x + threadIdx.x;
    if (n >= (long)NB * 2 * CC * HW) return;
    const int px = (int)(n & 127);
    const int py = (int)((n >> 7) & 127);
    const int ch = (int)((n >> 14) % (2 * CC));
    const float* base = in + ((n >> 14) << 14);
    float acc = 0.f;
    #pragma unroll
    for (int t = 0; t < 9; t++) {
        int dy = t / 3 - 1, dx = t % 3 - 1;
        int iy = py + dy, ix = px + dx;
        if (iy >= 0 && iy < IMH && ix >= 0 && ix < IMW)
            acc += w[ch * 9 + t] * base[iy * IMW + ix];
    }
    out[n] = acc;
}

// ---------------- gram + norms ---------------------------------------------
__global__ void gram(const float* __restrict__ q, const float* __restrict__ k,
                     float* __restrict__ Sp, float* __restrict__ nqp,
                     float* __restrict__ nkp) {
    const int ch = blockIdx.x, h = blockIdx.y, b = blockIdx.z;
    const int tid = threadIdx.x;               // 576
    const int c = tid / HD, d = tid % HD;
    __shared__ float sq[128][HD + 1];
    __shared__ float sk[128][HD + 1];
    const float* qb = q + ((long)b * CC + h * HD) * HW;
    const float* kb = k + ((long)b * 2 * CC + h * HD) * HW;

    float acc = 0.f, aq = 0.f, ak = 0.f;
    const int e_begin = ch * (HW / CHG), e_end = e_begin + HW / CHG;
    for (int e0 = e_begin; e0 < e_end; e0 += 128) {
        __syncthreads();
        for (int l = tid; l < HD * 128; l += 576) {
            int r = l >> 7, e = l & 127;
            sq[e][r] = qb[(long)r * HW + e0 + e];
            sk[e][r] = kb[(long)r * HW + e0 + e];
        }
        __syncthreads();
        #pragma unroll 8
        for (int e = 0; e < 128; e++) {
            float qa = sq[e][c], kv = sk[e][d];
            acc = fmaf(qa, kv, acc);
            if (c == d) { aq = fmaf(qa, qa, aq); ak = fmaf(kv, kv, ak); }
        }
    }
    long base = ((long)b * NHEADS + h) * CHG + ch;
    Sp[base * (HD * HD) + tid] = acc;
    if (c == d) { nqp[base * HD + c] = aq; nkp[base * HD + c] = ak; }
}

// ---------------- softmax + MoH[b][o][i] = proj*blockdiag(attn) ------------
__global__ void attn_m(const float* __restrict__ Sp, const float* __restrict__ nqp,
                       const float* __restrict__ nkp, const float* __restrict__ temp,
                       const float* __restrict__ proj, __half* __restrict__ MoH) {
    const int h = blockIdx.x, b = blockIdx.y, tid = threadIdx.x;  // 576 threads
    __shared__ float sA[HD][HD + 1];
    __shared__ float snq[HD], snk[HD];
    const long base = ((long)b * NHEADS + h) * CHG;

    float s = 0.f;
    for (int cc = 0; cc < CHG; cc++) s += Sp[(base + cc) * (HD * HD) + tid];

    if (tid < HD) {
        float a = 0.f, kk = 0.f;
        for (int cc = 0; cc < CHG; cc++) {
            a  += nqp[(base + cc) * HD + tid];
            kk += nkp[(base + cc) * HD + tid];
        }
        snq[tid] = fmaxf(sqrtf(a),  1e-12f);
        snk[tid] = fmaxf(sqrtf(kk), 1e-12f);
    }
    __syncthreads();
    {
        int c = tid / HD, d = tid % HD;
        sA[c][d] = s / (snq[c] * snk[d]) * temp[h];
    }
    __syncthreads();
    if (tid < HD) {
        float mx = -1e30f;
        for (int d = 0; d < HD; d++) mx = fmaxf(mx, sA[tid][d]);
        float sum = 0.f;
        for (int d = 0; d < HD; d++) { float e = expf(sA[tid][d] - mx); sA[tid][d] = e; sum += e; }
        float inv = 1.f / sum;
        for (int d = 0; d < HD; d++) sA[tid][d] *= inv;
    }
    __syncthreads();
    for (int l = tid; l < HD * CC; l += 576) {
        int d = l / CC, o = l % CC;
        float acc = 0.f;
        #pragma unroll
        for (int c = 0; c < HD; c++) acc += proj[o * CC + h * HD + c] * sA[c][d];
        MoH[(long)b * CC * CC + (long)o * CC + h * HD + d] = __float2half(acc);
    }
}

// ---------------- launch ----------------------------------------------------
extern "C" void kernel_launch(void* const* d_in, const int* in_sizes, int n_in,
                              void* d_out, int out_size) {
    const float* x    = (const float*)d_in[0];
    const float* y    = (const float*)d_in[1];
    const float* temp = (const float*)d_in[2];
    const float* kvw  = (const float*)d_in[3];
    const float* kvdw = (const float*)d_in[4];
    const float* qw   = (const float*)d_in[5];
    const float* qdw  = (const float*)d_in[6];
    const float* proj = (const float*)d_in[7];
    float* out = (float*)d_out;

    __half *xH, *yTpH, *vH, *w2H, *kvwH, *MoH;
    float *kv1, *kv, *q, *Sp, *nqp, *nkp;
    cudaGetSymbolAddress((void**)&xH,   g_xH);
    cudaGetSymbolAddress((void**)&yTpH, g_yTpH);
    cudaGetSymbolAddress((void**)&vH,   g_vH);
    cudaGetSymbolAddress((void**)&w2H,  g_w2H);
    cudaGetSymbolAddress((void**)&kvwH, g_kvwH);
    cudaGetSymbolAddress((void**)&MoH,  g_MoH);
    cudaGetSymbolAddress((void**)&kv1,  g_kv1);
    cudaGetSymbolAddress((void**)&kv,   g_kv);
    cudaGetSymbolAddress((void**)&q,    g_q);
    cudaGetSymbolAddress((void**)&Sp,   g_Sp);
    cudaGetSymbolAddress((void**)&nqp,  g_nqp);
    cudaGetSymbolAddress((void**)&nkp,  g_nkp);

    cudaFuncSetAttribute(gemm_h, cudaFuncAttributeMaxDynamicSharedMemorySize, SM_TOTAL);

    // weights -> half
    conv_h<<<(2 * CC * CC + 255) / 256, 256>>>(kvw, kvwH, 2 * CC * CC);
    build_w2h<<<dim3(CC, 9), CC>>>(qdw, qw, w2H);

    // activations -> K-contiguous half layouts
    transpose_h<<<dim3(HW / 32, CC / 32, NB), dim3(32, 8)>>>(x, (long)CC * HW, xH, (long)HW * CC, 0);
    cudaMemsetAsync(yTpH, 0, (size_t)NB * YSLOTS * CC * sizeof(__half), 0);
    transpose_h<<<dim3(HW / 32, CC / 32, NB), dim3(32, 8)>>>(y, (long)CC * HW,
                                                             yTpH + (long)PADW * CC, (long)YSLOTS * CC, 1);

    // kv = 1x1 conv (tensor): C rows 0..383 over two y-blocks
    gemm_h<<<dim3(128, 2, NB), 256, SM_TOTAL>>>(xH, kvwH, kv1,
        (long)HW * CC, 0L, (long)2 * CC * HW, CC, 6, 0);
    // depthwise 3x3 (fp32)
    dwconv<<<(int)(((long)NB * 2 * CC * HW + 255) / 256), 256>>>(kv1, kvdw, kv);
    // v -> half [p][c]
    transpose_h<<<dim3(HW / 32, CC / 32, NB), dim3(32, 8)>>>(kv + (long)CC * HW, (long)2 * CC * HW,
                                                             vH, (long)HW * CC, 0);
    // fused q conv: 54 chunks = 9 taps x 6 ch-chunks
    gemm_h<<<dim3(IMH, 1, NB), 256, SM_TOTAL>>>(yTpH, w2H, q,
        (long)YSLOTS * CC, 0L, (long)CC * HW, KQ, 54, 1);
    // gram + norms
    gram<<<dim3(CHG, NHEADS, NB), 576>>>(q, kv, Sp, nqp, nkp);
    // softmax + fused proj*attn (half, K-contiguous)
    attn_m<<<dim3(NHEADS, NB), 576>>>(Sp, nqp, nkp, temp, proj, MoH);
    // out = (proj*attn) @ v
    gemm_h<<<dim3(128, 1, NB), 256, SM_TOTAL>>>(vH, MoH, out,
        (long)HW * CC, (long)CC * CC, (long)CC * HW, CC, 6, 0);
}

// round 5
// speedup vs baseline: 3.7718x; 1.4500x over previous
#include <cuda_runtime.h>
#include <cuda_fp16.h>
#include <math.h>
#include <stdint.h>

#define HW    16384
#define IMW   128
#define IMH   128
#define CC    192
#define NB    8
#define NHEADS 8
#define HD    24
#define CHG   8
#define KQ    (9*CC)            // 1728
#define PADW  130
#define PADHW (IMH*PADW)        // 16640
#define YSLOTS (PADHW + 2*PADW) // guard rows top+bottom

// ---------------- scratch ---------------------------------------------------
__device__ __align__(1024) __half g_xH  [(size_t)NB*HW*CC];
__device__ __align__(1024) __half g_yTpH[(size_t)NB*YSLOTS*CC];
__device__ __align__(1024) __half g_kv1H[(size_t)NB*2*CC*HW];
__device__ __align__(1024) __half g_kH  [(size_t)NB*CC*HW + 16*HW]; // +slack rows
__device__ __align__(1024) __half g_vcmH[(size_t)NB*CC*HW];
__device__ __align__(1024) __half g_vH  [(size_t)NB*HW*CC];
__device__ __align__(1024) __half g_qH  [(size_t)NB*CC*HW + 16*HW]; // +slack rows
__device__ __align__(1024) __half g_w2H [(size_t)CC*KQ];
__device__ __align__(1024) __half g_kvwH[2*CC*CC];
__device__ __align__(1024) __half g_MoH [(size_t)NB*CC*CC];
__device__ float g_Sp [(size_t)NB*NHEADS*CHG*HD*HD];
__device__ float g_nqF[(size_t)NB*CC];
__device__ float g_nkF[(size_t)NB*CC];

__device__ __forceinline__ uint32_t smem_u32(const void* p) {
    uint32_t a;
    asm("{ .reg .u64 t; cvta.to.shared.u64 t, %1; cvt.u32.u64 %0, t; }"
        : "=r"(a) : "l"(p));
    return a;
}

#define LDSM_X4(r0, r1, r2, r3, addr) \
    asm volatile("ldmatrix.sync.aligned.m8n8.x4.shared.b16 {%0,%1,%2,%3}, [%4];" \
                 : "=r"(r0), "=r"(r1), "=r"(r2), "=r"(r3) : "r"(addr))

#define MMA16816(d, a, b0v, b1v) \
    asm volatile("mma.sync.aligned.m16n8k16.row.col.f32.f16.f16.f32 " \
                 "{%0,%1,%2,%3}, {%4,%5,%6,%7}, {%8,%9}, {%0,%1,%2,%3};" \
                 : "+f"((d)[0]), "+f"((d)[1]), "+f"((d)[2]), "+f"((d)[3]) \
                 : "r"((a)[0]), "r"((a)[1]), "r"((a)[2]), "r"((a)[3]), \
                   "r"(b0v), "r"(b1v))

#define CP16(dst, src) \
    asm volatile("cp.async.cg.shared.global [%0], [%1], 16;" \
                 :: "r"(dst), "l"(src))

// ---------------- fp16 mma GEMM --------------------------------------------
// C[o][p] = sum_k A[p][k] * B[o][k]; 256 thr, tile 128(p)x192(o), BK=32,
// cp.async double buffer. conv_mode: A in padded y layout, 54 chunks.
#define SM_STAGE 25600
#define SM_TOTAL (2*SM_STAGE)

__device__ __forceinline__ void stage_load(
    uint32_t sb, int s, const __half* __restrict__ Ag,
    const __half* __restrict__ Bg, int c, int conv_mode, int KB, int o0, int tid)
{
    int t  = c / 6;
    int i0 = (c - t * 6) * 32;
    long arow;
    if (conv_mode) {
        int dy = t / 3 - 1, dx = t - t / 3 * 3 - 1;
        arow = (long)(blockIdx.x + dy + 1) * PADW + 1 + dx;
    } else {
        arow = (long)blockIdx.x * 128;
    }
    uint32_t sA = sb + s * SM_STAGE;
    uint32_t sB = sA + 10240;
    #pragma unroll
    for (int it = 0; it < 2; it++) {
        int ck = tid + it * 256;
        int r = ck >> 2, off = ck & 3;
        uint64_t src = __cvta_generic_to_global(Ag + (arow + r) * (long)CC + i0 + off * 8);
        CP16(sA + r * 80 + off * 16, src);
    }
    #pragma unroll
    for (int it = 0; it < 3; it++) {
        int ck = tid + it * 256;
        int r = ck >> 2, off = ck & 3;
        uint64_t src = __cvta_generic_to_global(Bg + (long)(o0 + r) * KB + c * 32 + off * 8);
        CP16(sB + r * 80 + off * 16, src);
    }
    asm volatile("cp.async.commit_group;");
}

__global__ __launch_bounds__(256)
void gemm_h(const __half* __restrict__ A, const __half* __restrict__ B,
            void* __restrict__ Cv, long aBatch, long bBatch, long cBatch,
            int KB, int nc, int conv_mode, int outHalf)
{
    extern __shared__ __align__(128) char sm[];
    const uint32_t sb = smem_u32(sm);
    const int tid = threadIdx.x, lane = tid & 31, wid = tid >> 5;
    const int wp = wid & 1, wo = wid >> 1;
    const int b = blockIdx.z, o0 = blockIdx.y * 192;
    const __half* Ag = A + (long)b * aBatch;
    const __half* Bg = B + (long)b * bBatch;

    float acc[4][6][4];
    #pragma unroll
    for (int mf = 0; mf < 4; mf++)
        #pragma unroll
        for (int nf = 0; nf < 6; nf++)
            #pragma unroll
            for (int r = 0; r < 4; r++) acc[mf][nf][r] = 0.f;

    stage_load(sb, 0, Ag, Bg, 0, conv_mode, KB, o0, tid);

    const int t8 = lane >> 3, r8 = lane & 7;
    const int am = (t8 & 1) * 8 + r8, ak = (t8 >> 1) * 8;
    const int bn = (t8 >> 1) * 8 + r8, bk = (t8 & 1) * 8;

    for (int c = 0; c < nc; c++) {
        if (c + 1 < nc) {
            stage_load(sb, (c + 1) & 1, Ag, Bg, c + 1, conv_mode, KB, o0, tid);
            asm volatile("cp.async.wait_group 1;");
        } else {
            asm volatile("cp.async.wait_group 0;");
        }
        __syncthreads();
        uint32_t sA = sb + (c & 1) * SM_STAGE;
        uint32_t sB = sA + 10240;
        #pragma unroll
        for (int ks = 0; ks < 2; ks++) {
            uint32_t a[4][4], bf[3][4];
            #pragma unroll
            for (int mf = 0; mf < 4; mf++) {
                uint32_t addr = sA + (uint32_t)(((wp * 64 + mf * 16 + am) * 40 + ks * 16 + ak) * 2);
                LDSM_X4(a[mf][0], a[mf][1], a[mf][2], a[mf][3], addr);
            }
            #pragma unroll
            for (int pp = 0; pp < 3; pp++) {
                uint32_t addr = sB + (uint32_t)(((wo * 48 + pp * 16 + bn) * 40 + ks * 16 + bk) * 2);
                LDSM_X4(bf[pp][0], bf[pp][1], bf[pp][2], bf[pp][3], addr);
            }
            #pragma unroll
            for (int mf = 0; mf < 4; mf++)
                #pragma unroll
                for (int nf = 0; nf < 6; nf++)
                    MMA16816(acc[mf][nf], a[mf], bf[nf >> 1][(nf & 1) * 2],
                             bf[nf >> 1][(nf & 1) * 2 + 1]);
        }
        __syncthreads();
    }

    const int prow = blockIdx.x * 128 + wp * 64 + (lane >> 2);
    const int ocol = o0 + wo * 48 + (lane & 3) * 2;
    if (outHalf) {
        __half* Cb = (__half*)Cv + (long)b * cBatch;
        #pragma unroll
        for (int mf = 0; mf < 4; mf++)
            #pragma unroll
            for (int nf = 0; nf < 6; nf++) {
                int p = prow + mf * 16;
                int o = ocol + nf * 8;
                Cb[(long)o * HW + p]           = __float2half(acc[mf][nf][0]);
                Cb[(long)(o + 1) * HW + p]     = __float2half(acc[mf][nf][1]);
                Cb[(long)o * HW + p + 8]       = __float2half(acc[mf][nf][2]);
                Cb[(long)(o + 1) * HW + p + 8] = __float2half(acc[mf][nf][3]);
            }
    } else {
        float* Cb = (float*)Cv + (long)b * cBatch;
        #pragma unroll
        for (int mf = 0; mf < 4; mf++)
            #pragma unroll
            for (int nf = 0; nf < 6; nf++) {
                int p = prow + mf * 16;
                int o = ocol + nf * 8;
                Cb[(long)o * HW + p]           = acc[mf][nf][0];
                Cb[(long)(o + 1) * HW + p]     = acc[mf][nf][1];
                Cb[(long)o * HW + p + 8]       = acc[mf][nf][2];
                Cb[(long)(o + 1) * HW + p + 8] = acc[mf][nf][3];
            }
    }
}

// ---------------- producers -------------------------------------------------
__global__ void conv_h(const float* __restrict__ in, __half* __restrict__ out, int n) {
    int i = blockIdx.x * 256 + threadIdx.x;
    if (i < n) out[i] = __float2half(in[i]);
}

__global__ void build_w2h(const float* __restrict__ qdw, const float* __restrict__ qw,
                          __half* __restrict__ w2h) {
    int o = blockIdx.x, t = blockIdx.y, i = threadIdx.x;
    __shared__ float dw[CC];
    dw[i] = qdw[(o * CC + i) * 9 + t];
    __syncthreads();
    float acc = 0.f;
    #pragma unroll 4
    for (int m = 0; m < CC; m++) acc += dw[m] * qw[m * CC + i];
    w2h[(long)o * KQ + t * CC + i] = __float2half(acc);
}

// [b][c][hw] fp32 -> [b][slot][c] half
__global__ void transpose_h(const float* __restrict__ in, long inB,
                            __half* __restrict__ out, long outB, int pad)
{
    __shared__ float t[32][33];
    int b = blockIdx.z, px0 = blockIdx.x * 32, c0 = blockIdx.y * 32;
    int tx = threadIdx.x, ty = threadIdx.y;
    const float* ib = in + (long)b * inB;
    #pragma unroll
    for (int j = 0; j < 4; j++)
        t[ty + j * 8][tx] = ib[(long)(c0 + ty + j * 8) * HW + px0 + tx];
    __syncthreads();
    __half* ob = out + (long)b * outB;
    #pragma unroll
    for (int j = 0; j < 4; j++) {
        int px = px0 + ty + j * 8;
        long slot = pad ? (long)(px >> 7) * PADW + 1 + (px & 127) : px;
        ob[slot * CC + c0 + tx] = __float2half(t[tx][ty + j * 8]);
    }
}

// [b][c][p] half -> [b][p][c] half
__global__ void transpose_hh(const __half* __restrict__ in, __half* __restrict__ out)
{
    __shared__ __half t[32][33];
    int b = blockIdx.z, px0 = blockIdx.x * 32, c0 = blockIdx.y * 32;
    int tx = threadIdx.x, ty = threadIdx.y;
    const __half* ib = in + (long)b * CC * HW;
    #pragma unroll
    for (int j = 0; j < 4; j++)
        t[ty + j * 8][tx] = ib[(long)(c0 + ty + j * 8) * HW + px0 + tx];
    __syncthreads();
    __half* ob = out + (long)b * HW * CC;
    #pragma unroll
    for (int j = 0; j < 4; j++)
        ob[(long)(px0 + ty + j * 8) * CC + c0 + tx] = t[tx][ty + j * 8];
}

// ---------------- depthwise 3x3, half I/O, 8 px/thread ----------------------
__global__ __launch_bounds__(256)
void dwconv_h(const __half* __restrict__ in, const float* __restrict__ w,
              __half* __restrict__ kout, __half* __restrict__ vout)
{
    int g = blockIdx.x * 256 + threadIdx.x;
    int px8 = g & 15;
    int t1 = g >> 4;
    int py = t1 & 127;
    int t2 = t1 >> 7;            // b*384 + ch
    int ch = t2 % (2 * CC);
    int b  = t2 / (2 * CC);
    const __half* base = in + (long)t2 * HW + py * IMW + px8 * 8;

    float w9[9];
    #pragma unroll
    for (int t = 0; t < 9; t++) w9[t] = w[ch * 9 + t];

    float acc[8];
    #pragma unroll
    for (int j = 0; j < 8; j++) acc[j] = 0.f;

    #pragma unroll
    for (int dy = -1; dy <= 1; dy++) {
        int iy = py + dy;
        if (iy < 0 || iy >= IMH) continue;
        const __half* rp = base + dy * IMW;
        float v[10];
        uint4 mid = *(const uint4*)rp;
        const __half* mh = (const __half*)&mid;
        #pragma unroll
        for (int j = 0; j < 8; j++) v[j + 1] = __half2float(mh[j]);
        v[0] = (px8 > 0)  ? __half2float(rp[-1]) : 0.f;
        v[9] = (px8 < 15) ? __half2float(rp[8])  : 0.f;
        int tb = (dy + 1) * 3;
        #pragma unroll
        for (int j = 0; j < 8; j++)
            acc[j] += w9[tb] * v[j] + w9[tb + 1] * v[j + 1] + w9[tb + 2] * v[j + 2];
    }

    __half o8[8];
    #pragma unroll
    for (int j = 0; j < 8; j++) o8[j] = __float2half(acc[j]);
    int cl = (ch < CC) ? ch : ch - CC;
    __half* dst = ((ch < CC) ? kout : vout) + ((long)b * CC + cl) * HW + py * IMW + px8 * 8;
    *(uint4*)dst = *(const uint4*)o8;
}

// ---------------- norms: nq[b][c] = sum q^2 ---------------------------------
__global__ void norms_k(const __half* __restrict__ qH, const __half* __restrict__ kH,
                        float* __restrict__ nqF, float* __restrict__ nkF)
{
    int c = blockIdx.x, b = blockIdx.y, which = blockIdx.z;
    int tid = threadIdx.x;
    const __half2* p2 = (const __half2*)((which ? kH : qH) + ((long)b * CC + c) * HW);
    float s = 0.f;
    for (int i = tid; i < HW / 2; i += 256) {
        float2 f = __half22float2(p2[i]);
        s = fmaf(f.x, f.x, s); s = fmaf(f.y, f.y, s);
    }
    #pragma unroll
    for (int o = 16; o > 0; o >>= 1) s += __shfl_down_sync(0xffffffff, s, o);
    __shared__ float ws[8];
    if ((tid & 31) == 0) ws[tid >> 5] = s;
    __syncthreads();
    if (tid == 0) {
        float t = 0.f;
        #pragma unroll
        for (int i = 0; i < 8; i++) t += ws[i];
        (which ? nkF : nqF)[b * CC + c] = t;
    }
}

// ---------------- gram via mma: Sp[b,h,ch][c,d] partials --------------------
#define SK 264
#define GR_SMEM (2*32*SK*2)   // 33792 B

__global__ __launch_bounds__(256)
void gram_mma(const __half* __restrict__ qH, const __half* __restrict__ kH,
              float* __restrict__ Sp)
{
    extern __shared__ __align__(128) char gsm[];
    const uint32_t sb = smem_u32(gsm);
    const uint32_t qs = sb, ks_ = sb + 32 * SK * 2;
    const int tid = threadIdx.x, lane = tid & 31, w = tid >> 5;
    const int ch = blockIdx.x, h = blockIdx.y, b = blockIdx.z;
    const __half* qb = qH + ((long)b * CC + h * HD) * HW;
    const __half* kb = kH + ((long)b * CC + h * HD) * HW;
    const int k0 = ch * (HW / CHG);

    float acc[2][4][4];
    #pragma unroll
    for (int mt = 0; mt < 2; mt++)
        #pragma unroll
        for (int nf = 0; nf < 4; nf++)
            #pragma unroll
            for (int r = 0; r < 4; r++) acc[mt][nf][r] = 0.f;

    const int t8 = lane >> 3, r8 = lane & 7;
    const int am = (t8 & 1) * 8 + r8, ak = (t8 >> 1) * 8;
    const int bn = (t8 >> 1) * 8 + r8, bk = (t8 & 1) * 8;

    for (int kb0 = 0; kb0 < HW / CHG; kb0 += 256) {
        #pragma unroll
        for (int it = 0; it < 4; it++) {
            int cidx = tid + it * 256;
            int r = cidx >> 5, c2 = cidx & 31;
            CP16(qs + r * (SK * 2) + c2 * 16,
                 __cvta_generic_to_global(qb + (long)r * HW + k0 + kb0 + c2 * 8));
            CP16(ks_ + r * (SK * 2) + c2 * 16,
                 __cvta_generic_to_global(kb + (long)r * HW + k0 + kb0 + c2 * 8));
        }
        asm volatile("cp.async.commit_group;");
        asm volatile("cp.async.wait_group 0;");
        __syncthreads();
        #pragma unroll
        for (int kst = 0; kst < 2; kst++) {
            int wk = w * 32 + kst * 16;
            uint32_t a[2][4], bf[2][4];
            #pragma unroll
            for (int mt = 0; mt < 2; mt++) {
                uint32_t addr = qs + (uint32_t)(((mt * 16 + am) * SK + wk + ak) * 2);
                LDSM_X4(a[mt][0], a[mt][1], a[mt][2], a[mt][3], addr);
            }
            #pragma unroll
            for (int pp = 0; pp < 2; pp++) {
                uint32_t addr = ks_ + (uint32_t)(((pp * 16 + bn) * SK + wk + bk) * 2);
                LDSM_X4(bf[pp][0], bf[pp][1], bf[pp][2], bf[pp][3], addr);
            }
            #pragma unroll
            for (int mt = 0; mt < 2; mt++)
                #pragma unroll
                for (int nf = 0; nf < 4; nf++)
                    MMA16816(acc[mt][nf], a[mt], bf[nf >> 1][(nf & 1) * 2],
                             bf[nf >> 1][(nf & 1) * 2 + 1]);
        }
        __syncthreads();
    }

    float* red = (float*)gsm;   // 8*32*32*4 = 32768 <= GR_SMEM
    #pragma unroll
    for (int mt = 0; mt < 2; mt++)
        #pragma unroll
        for (int nf = 0; nf < 4; nf++)
            #pragma unroll
            for (int fr = 0; fr < 4; fr++) {
                int c = mt * 16 + (lane >> 2) + ((fr & 2) ? 8 : 0);
                int d = nf * 8 + (lane & 3) * 2 + (fr & 1);
                red[w * 1024 + c * 32 + d] = acc[mt][nf][fr];
            }
    __syncthreads();
    long base = (((long)b * NHEADS + h) * CHG + ch) * (HD * HD);
    for (int e = tid; e < 32 * HD; e += 256) {
        int c = e / HD, d = e % HD;
        if (c < HD) {
            float s = 0.f;
            #pragma unroll
            for (int ww = 0; ww < 8; ww++) s += red[ww * 1024 + c * 32 + d];
            Sp[base + c * HD + d] = s;
        }
    }
}

// ---------------- softmax + MoH = proj*blockdiag(attn) ----------------------
__global__ void attn_m(const float* __restrict__ Sp, const float* __restrict__ nqF,
                       const float* __restrict__ nkF, const float* __restrict__ temp,
                       const float* __restrict__ proj, __half* __restrict__ MoH) {
    const int h = blockIdx.x, b = blockIdx.y, tid = threadIdx.x;  // 576 threads
    __shared__ float sA[HD][HD + 1];
    __shared__ float snq[HD], snk[HD];
    const long base = ((long)b * NHEADS + h) * CHG;

    float s = 0.f;
    for (int cc = 0; cc < CHG; cc++) s += Sp[(base + cc) * (HD * HD) + tid];

    if (tid < HD) {
        snq[tid] = fmaxf(sqrtf(nqF[b * CC + h * HD + tid]), 1e-12f);
        snk[tid] = fmaxf(sqrtf(nkF[b * CC + h * HD + tid]), 1e-12f);
    }
    __syncthreads();
    {
        int c = tid / HD, d = tid % HD;
        sA[c][d] = s / (snq[c] * snk[d]) * temp[h];
    }
    __syncthreads();
    if (tid < HD) {
        float mx = -1e30f;
        for (int d = 0; d < HD; d++) mx = fmaxf(mx, sA[tid][d]);
        float sum = 0.f;
        for (int d = 0; d < HD; d++) { float e = expf(sA[tid][d] - mx); sA[tid][d] = e; sum += e; }
        float inv = 1.f / sum;
        for (int d = 0; d < HD; d++) sA[tid][d] *= inv;
    }
    __syncthreads();
    for (int l = tid; l < HD * CC; l += 576) {
        int d = l / CC, o = l % CC;
        float acc = 0.f;
        #pragma unroll
        for (int c = 0; c < HD; c++) acc += proj[o * CC + h * HD + c] * sA[c][d];
        MoH[(long)b * CC * CC + (long)o * CC + h * HD + d] = __float2half(acc);
    }
}

// ---------------- launch ----------------------------------------------------
extern "C" void kernel_launch(void* const* d_in, const int* in_sizes, int n_in,
                              void* d_out, int out_size) {
    const float* x    = (const float*)d_in[0];
    const float* y    = (const float*)d_in[1];
    const float* temp = (const float*)d_in[2];
    const float* kvw  = (const float*)d_in[3];
    const float* kvdw = (const float*)d_in[4];
    const float* qw   = (const float*)d_in[5];
    const float* qdw  = (const float*)d_in[6];
    const float* proj = (const float*)d_in[7];
    float* out = (float*)d_out;

    __half *xH, *yTpH, *kv1H, *kH, *vcmH, *vH, *qH, *w2H, *kvwH, *MoH;
    float *Sp, *nqF, *nkF;
    cudaGetSymbolAddress((void**)&xH,   g_xH);
    cudaGetSymbolAddress((void**)&yTpH, g_yTpH);
    cudaGetSymbolAddress((void**)&kv1H, g_kv1H);
    cudaGetSymbolAddress((void**)&kH,   g_kH);
    cudaGetSymbolAddress((void**)&vcmH, g_vcmH);
    cudaGetSymbolAddress((void**)&vH,   g_vH);
    cudaGetSymbolAddress((void**)&qH,   g_qH);
    cudaGetSymbolAddress((void**)&w2H,  g_w2H);
    cudaGetSymbolAddress((void**)&kvwH, g_kvwH);
    cudaGetSymbolAddress((void**)&MoH,  g_MoH);
    cudaGetSymbolAddress((void**)&Sp,   g_Sp);
    cudaGetSymbolAddress((void**)&nqF,  g_nqF);
    cudaGetSymbolAddress((void**)&nkF,  g_nkF);

    cudaFuncSetAttribute(gemm_h, cudaFuncAttributeMaxDynamicSharedMemorySize, SM_TOTAL);

    // weights -> half
    conv_h<<<(2 * CC * CC + 255) / 256, 256>>>(kvw, kvwH, 2 * CC * CC);
    build_w2h<<<dim3(CC, 9), CC>>>(qdw, qw, w2H);

    // activations -> K-contiguous half layouts
    transpose_h<<<dim3(HW / 32, CC / 32, NB), dim3(32, 8)>>>(x, (long)CC * HW, xH, (long)HW * CC, 0);
    cudaMemsetAsync(yTpH, 0, (size_t)NB * YSLOTS * CC * sizeof(__half), 0);
    transpose_h<<<dim3(HW / 32, CC / 32, NB), dim3(32, 8)>>>(y, (long)CC * HW,
                                                             yTpH + (long)PADW * CC, (long)YSLOTS * CC, 1);

    // kv = 1x1 conv (half out)
    gemm_h<<<dim3(128, 2, NB), 256, SM_TOTAL>>>(xH, kvwH, kv1H,
        (long)HW * CC, 0L, (long)2 * CC * HW, CC, 6, 0, 1);
    // depthwise 3x3: -> kH (ch-major) + vcmH (ch-major)
    dwconv_h<<<NB * 2 * CC * HW / 8 / 256, 256>>>(kv1H, kvdw, kH, vcmH);
    // v -> [p][c]
    transpose_hh<<<dim3(HW / 32, CC / 32, NB), dim3(32, 8)>>>(vcmH, vH);
    // fused q conv (half out)
    gemm_h<<<dim3(IMH, 1, NB), 256, SM_TOTAL>>>(yTpH, w2H, qH,
        (long)YSLOTS * CC, 0L, (long)CC * HW, KQ, 54, 1, 1);
    // norms + gram (mma)
    norms_k<<<dim3(CC, NB, 2), 256>>>(qH, kH, nqF, nkF);
    gram_mma<<<dim3(CHG, NHEADS, NB), 256, GR_SMEM>>>(qH, kH, Sp);
    // softmax + fused proj*attn
    attn_m<<<dim3(NHEADS, NB), 576>>>(Sp, nqF, nkF, temp, proj, MoH);
    // out = (proj*attn) @ v (fp32 out)
    gemm_h<<<dim3(128, 1, NB), 256, SM_TOTAL>>>(vH, MoH, out,
        (long)HW * CC, (long)CC * CC, (long)CC * HW, CC, 6, 0, 0);
}

// round 6
// speedup vs baseline: 3.8359x; 1.0170x over previous
#include <cuda_runtime.h>
#include <cuda_fp16.h>
#include <math.h>
#include <stdint.h>

#define HW    16384
#define IMW   128
#define IMH   128
#define CC    192
#define NB    8
#define NHEADS 8
#define HD    24
#define CHG   8
#define KQ    (9*CC)            // 1728
#define PADW  130
#define PADHW (IMH*PADW)        // 16640
#define YSLOTS (PADHW + 2*PADW) // guard rows top+bottom

// ---------------- scratch ---------------------------------------------------
__device__ __align__(1024) __half g_xH  [(size_t)NB*HW*CC];
__device__ __align__(1024) __half g_yTpH[(size_t)NB*YSLOTS*CC];
__device__ __align__(1024) __half g_kv1H[(size_t)NB*2*CC*HW];
__device__ __align__(1024) __half g_kH  [(size_t)NB*CC*HW + 16*HW];
__device__ __align__(1024) __half g_vcmH[(size_t)NB*CC*HW];
__device__ __align__(1024) __half g_vH  [(size_t)NB*HW*CC];
__device__ __align__(1024) __half g_qH  [(size_t)NB*CC*HW + 16*HW];
__device__ __align__(1024) __half g_w2H [(size_t)CC*KQ];
__device__ __align__(1024) __half g_kvwH[2*CC*CC];
__device__ __align__(1024) __half g_MoH [(size_t)NB*CC*CC];
__device__ float g_Sp [(size_t)NB*NHEADS*CHG*HD*HD];
__device__ float g_nqF[(size_t)NB*CC];
__device__ float g_nkF[(size_t)NB*CC];

__device__ __forceinline__ uint32_t smem_u32(const void* p) {
    uint32_t a;
    asm("{ .reg .u64 t; cvta.to.shared.u64 t, %1; cvt.u32.u64 %0, t; }"
        : "=r"(a) : "l"(p));
    return a;
}

#define LDSM_X4(r0, r1, r2, r3, addr) \
    asm volatile("ldmatrix.sync.aligned.m8n8.x4.shared.b16 {%0,%1,%2,%3}, [%4];" \
                 : "=r"(r0), "=r"(r1), "=r"(r2), "=r"(r3) : "r"(addr))

#define MMA16816(d, a, b0v, b1v) \
    asm volatile("mma.sync.aligned.m16n8k16.row.col.f32.f16.f16.f32 " \
                 "{%0,%1,%2,%3}, {%4,%5,%6,%7}, {%8,%9}, {%0,%1,%2,%3};" \
                 : "+f"((d)[0]), "+f"((d)[1]), "+f"((d)[2]), "+f"((d)[3]) \
                 : "r"((a)[0]), "r"((a)[1]), "r"((a)[2]), "r"((a)[3]), \
                   "r"(b0v), "r"(b1v))

#define CP16(dst, src) \
    asm volatile("cp.async.cg.shared.global [%0], [%1], 16;" \
                 :: "r"(dst), "l"(src))

// ---------------- fp16 mma GEMM, 3-stage single-barrier pipeline -----------
// C[o][p] = sum_k A[p][k] * B[o][k]; 256 thr, tile 128(p)x192(o), BK=32.
#define SM_STAGE 25600
#define SM_TOTAL (3*SM_STAGE)

__device__ __forceinline__ void stage_load(
    uint32_t sb, int slot, const __half* __restrict__ Ag,
    const __half* __restrict__ Bg, int c, int conv_mode, int KB, int o0, int tid)
{
    int t  = c / 6;
    int i0 = (c - t * 6) * 32;
    long arow;
    if (conv_mode) {
        int dy = t / 3 - 1, dx = t - t / 3 * 3 - 1;
        arow = (long)(blockIdx.x + dy + 1) * PADW + 1 + dx;
    } else {
        arow = (long)blockIdx.x * 128;
    }
    uint32_t sA = sb + slot * SM_STAGE;
    uint32_t sB = sA + 10240;
    #pragma unroll
    for (int it = 0; it < 2; it++) {
        int ck = tid + it * 256;
        int r = ck >> 2, off = ck & 3;
        uint64_t src = __cvta_generic_to_global(Ag + (arow + r) * (long)CC + i0 + off * 8);
        CP16(sA + r * 80 + off * 16, src);
    }
    #pragma unroll
    for (int it = 0; it < 3; it++) {
        int ck = tid + it * 256;
        int r = ck >> 2, off = ck & 3;
        uint64_t src = __cvta_generic_to_global(Bg + (long)(o0 + r) * KB + c * 32 + off * 8);
        CP16(sB + r * 80 + off * 16, src);
    }
    asm volatile("cp.async.commit_group;");
}

__global__ __launch_bounds__(256)
void gemm_h(const __half* __restrict__ A, const __half* __restrict__ B,
            void* __restrict__ Cv, long aBatch, long bBatch, long cBatch,
            int KB, int nc, int conv_mode, int outHalf)
{
    extern __shared__ __align__(128) char sm[];
    const uint32_t sb = smem_u32(sm);
    const int tid = threadIdx.x, lane = tid & 31, wid = tid >> 5;
    const int wp = wid & 1, wo = wid >> 1;
    const int b = blockIdx.z, o0 = blockIdx.y * 192;
    const __half* Ag = A + (long)b * aBatch;
    const __half* Bg = B + (long)b * bBatch;

    float acc[4][6][4];
    #pragma unroll
    for (int mf = 0; mf < 4; mf++)
        #pragma unroll
        for (int nf = 0; nf < 6; nf++)
            #pragma unroll
            for (int r = 0; r < 4; r++) acc[mf][nf][r] = 0.f;

    stage_load(sb, 0, Ag, Bg, 0, conv_mode, KB, o0, tid);
    if (nc > 1) stage_load(sb, 1, Ag, Bg, 1, conv_mode, KB, o0, tid);

    const int t8 = lane >> 3, r8 = lane & 7;
    const int am = (t8 & 1) * 8 + r8, ak = (t8 >> 1) * 8;
    const int bn = (t8 >> 1) * 8 + r8, bk = (t8 & 1) * 8;

    int slot = 0;
    for (int c = 0; c < nc; c++) {
        if (c + 1 < nc) asm volatile("cp.async.wait_group 1;");
        else            asm volatile("cp.async.wait_group 0;");
        __syncthreads();
        if (c + 2 < nc) {
            int ns = slot + 2; if (ns >= 3) ns -= 3;
            stage_load(sb, ns, Ag, Bg, c + 2, conv_mode, KB, o0, tid);
        }
        uint32_t sA = sb + slot * SM_STAGE;
        uint32_t sB = sA + 10240;
        #pragma unroll
        for (int ks = 0; ks < 2; ks++) {
            uint32_t a[4][4], bf[3][4];
            #pragma unroll
            for (int mf = 0; mf < 4; mf++) {
                uint32_t addr = sA + (uint32_t)(((wp * 64 + mf * 16 + am) * 40 + ks * 16 + ak) * 2);
                LDSM_X4(a[mf][0], a[mf][1], a[mf][2], a[mf][3], addr);
            }
            #pragma unroll
            for (int pp = 0; pp < 3; pp++) {
                uint32_t addr = sB + (uint32_t)(((wo * 48 + pp * 16 + bn) * 40 + ks * 16 + bk) * 2);
                LDSM_X4(bf[pp][0], bf[pp][1], bf[pp][2], bf[pp][3], addr);
            }
            #pragma unroll
            for (int mf = 0; mf < 4; mf++)
                #pragma unroll
                for (int nf = 0; nf < 6; nf++)
                    MMA16816(acc[mf][nf], a[mf], bf[nf >> 1][(nf & 1) * 2],
                             bf[nf >> 1][(nf & 1) * 2 + 1]);
        }
        if (++slot >= 3) slot = 0;
    }

    const int prow = blockIdx.x * 128 + wp * 64 + (lane >> 2);
    const int ocol = o0 + wo * 48 + (lane & 3) * 2;
    if (outHalf) {
        __half* Cb = (__half*)Cv + (long)b * cBatch;
        #pragma unroll
        for (int mf = 0; mf < 4; mf++)
            #pragma unroll
            for (int nf = 0; nf < 6; nf++) {
                int p = prow + mf * 16;
                int o = ocol + nf * 8;
                Cb[(long)o * HW + p]           = __float2half(acc[mf][nf][0]);
                Cb[(long)(o + 1) * HW + p]     = __float2half(acc[mf][nf][1]);
                Cb[(long)o * HW + p + 8]       = __float2half(acc[mf][nf][2]);
                Cb[(long)(o + 1) * HW + p + 8] = __float2half(acc[mf][nf][3]);
            }
    } else {
        float* Cb = (float*)Cv + (long)b * cBatch;
        #pragma unroll
        for (int mf = 0; mf < 4; mf++)
            #pragma unroll
            for (int nf = 0; nf < 6; nf++) {
                int p = prow + mf * 16;
                int o = ocol + nf * 8;
                Cb[(long)o * HW + p]           = acc[mf][nf][0];
                Cb[(long)(o + 1) * HW + p]     = acc[mf][nf][1];
                Cb[(long)o * HW + p + 8]       = acc[mf][nf][2];
                Cb[(long)(o + 1) * HW + p + 8] = acc[mf][nf][3];
            }
    }
}

// ---------------- producers -------------------------------------------------
__global__ void conv_h(const float* __restrict__ in, __half* __restrict__ out, int n) {
    int i = blockIdx.x * 256 + threadIdx.x;
    if (i < n) out[i] = __float2half(in[i]);
}

__global__ void build_w2h(const float* __restrict__ qdw, const float* __restrict__ qw,
                          __half* __restrict__ w2h) {
    int o = blockIdx.x, t = blockIdx.y, i = threadIdx.x;
    __shared__ float dw[CC];
    dw[i] = qdw[(o * CC + i) * 9 + t];
    __syncthreads();
    float acc = 0.f;
    #pragma unroll 4
    for (int m = 0; m < CC; m++) acc += dw[m] * qw[m * CC + i];
    w2h[(long)o * KQ + t * CC + i] = __float2half(acc);
}

// zero the guard rows + pad columns of yTpH (interior is fully overwritten)
#define NPAD 516   // 130 top + 130 bottom + 128*2 side slots
__global__ void pad_zero(__half* __restrict__ yTp) {
    int i = blockIdx.x * 256 + threadIdx.x;
    if (i >= NB * NPAD * CC) return;
    int c = i % CC;
    int r = (i / CC) % NPAD;
    int b = i / (CC * NPAD);
    long slot;
    if (r < 130) slot = r;
    else if (r < 260) slot = (long)PADW * (IMH + 1) + (r - 130);
    else { int j = r - 260; slot = (long)PADW * (1 + (j >> 1)) + ((j & 1) ? PADW - 1 : 0); }
    yTp[((long)b * YSLOTS + slot) * CC + c] = __float2half(0.f);
}

// [b][c][hw] fp32 -> [b][slot][c] half
__global__ void transpose_h(const float* __restrict__ in, long inB,
                            __half* __restrict__ out, long outB, int pad)
{
    __shared__ float t[32][33];
    int b = blockIdx.z, px0 = blockIdx.x * 32, c0 = blockIdx.y * 32;
    int tx = threadIdx.x, ty = threadIdx.y;
    const float* ib = in + (long)b * inB;
    #pragma unroll
    for (int j = 0; j < 4; j++)
        t[ty + j * 8][tx] = ib[(long)(c0 + ty + j * 8) * HW + px0 + tx];
    __syncthreads();
    __half* ob = out + (long)b * outB;
    #pragma unroll
    for (int j = 0; j < 4; j++) {
        int px = px0 + ty + j * 8;
        long slot = pad ? (long)(px >> 7) * PADW + 1 + (px & 127) : px;
        ob[slot * CC + c0 + tx] = __float2half(t[tx][ty + j * 8]);
    }
}

// [b][c][p] half -> [b][p][c] half
__global__ void transpose_hh(const __half* __restrict__ in, __half* __restrict__ out)
{
    __shared__ __half t[32][33];
    int b = blockIdx.z, px0 = blockIdx.x * 32, c0 = blockIdx.y * 32;
    int tx = threadIdx.x, ty = threadIdx.y;
    const __half* ib = in + (long)b * CC * HW;
    #pragma unroll
    for (int j = 0; j < 4; j++)
        t[ty + j * 8][tx] = ib[(long)(c0 + ty + j * 8) * HW + px0 + tx];
    __syncthreads();
    __half* ob = out + (long)b * HW * CC;
    #pragma unroll
    for (int j = 0; j < 4; j++)
        ob[(long)(px0 + ty + j * 8) * CC + c0 + tx] = t[tx][ty + j * 8];
}

// ---------------- depthwise 3x3, half I/O, 8 px/thread ----------------------
__global__ __launch_bounds__(256)
void dwconv_h(const __half* __restrict__ in, const float* __restrict__ w,
              __half* __restrict__ kout, __half* __restrict__ vout)
{
    int g = blockIdx.x * 256 + threadIdx.x;
    int px8 = g & 15;
    int t1 = g >> 4;
    int py = t1 & 127;
    int t2 = t1 >> 7;
    int ch = t2 % (2 * CC);
    int b  = t2 / (2 * CC);
    const __half* base = in + (long)t2 * HW + py * IMW + px8 * 8;

    float w9[9];
    #pragma unroll
    for (int t = 0; t < 9; t++) w9[t] = w[ch * 9 + t];

    float acc[8];
    #pragma unroll
    for (int j = 0; j < 8; j++) acc[j] = 0.f;

    #pragma unroll
    for (int dy = -1; dy <= 1; dy++) {
        int iy = py + dy;
        if (iy < 0 || iy >= IMH) continue;
        const __half* rp = base + dy * IMW;
        float v[10];
        uint4 mid = *(const uint4*)rp;
        const __half* mh = (const __half*)&mid;
        #pragma unroll
        for (int j = 0; j < 8; j++) v[j + 1] = __half2float(mh[j]);
        v[0] = (px8 > 0)  ? __half2float(rp[-1]) : 0.f;
        v[9] = (px8 < 15) ? __half2float(rp[8])  : 0.f;
        int tb = (dy + 1) * 3;
        #pragma unroll
        for (int j = 0; j < 8; j++)
            acc[j] += w9[tb] * v[j] + w9[tb + 1] * v[j + 1] + w9[tb + 2] * v[j + 2];
    }

    __half o8[8];
    #pragma unroll
    for (int j = 0; j < 8; j++) o8[j] = __float2half(acc[j]);
    int cl = (ch < CC) ? ch : ch - CC;
    __half* dst = ((ch < CC) ? kout : vout) + ((long)b * CC + cl) * HW + py * IMW + px8 * 8;
    *(uint4*)dst = *(const uint4*)o8;
}

// ---------------- norms -----------------------------------------------------
__global__ void norms_k(const __half* __restrict__ qH, const __half* __restrict__ kH,
                        float* __restrict__ nqF, float* __restrict__ nkF)
{
    int c = blockIdx.x, b = blockIdx.y, which = blockIdx.z;
    int tid = threadIdx.x;
    const __half2* p2 = (const __half2*)((which ? kH : qH) + ((long)b * CC + c) * HW);
    float s = 0.f;
    for (int i = tid; i < HW / 2; i += 256) {
        float2 f = __half22float2(p2[i]);
        s = fmaf(f.x, f.x, s); s = fmaf(f.y, f.y, s);
    }
    #pragma unroll
    for (int o = 16; o > 0; o >>= 1) s += __shfl_down_sync(0xffffffff, s, o);
    __shared__ float ws[8];
    if ((tid & 31) == 0) ws[tid >> 5] = s;
    __syncthreads();
    if (tid == 0) {
        float t = 0.f;
        #pragma unroll
        for (int i = 0; i < 8; i++) t += ws[i];
        (which ? nkF : nqF)[b * CC + c] = t;
    }
}

// ---------------- gram via mma, double-buffered -----------------------------
#define SK 264
#define GR_STAGE (2*32*SK*2)     // q+k one stage = 33792 B
#define GR_SMEM  (2*GR_STAGE)    // 67584 B

__global__ __launch_bounds__(256)
void gram_mma(const __half* __restrict__ qH, const __half* __restrict__ kH,
              float* __restrict__ Sp)
{
    extern __shared__ __align__(128) char gsm[];
    const uint32_t sb = smem_u32(gsm);
    const int tid = threadIdx.x, lane = tid & 31, w = tid >> 5;
    const int ch = blockIdx.x, h = blockIdx.y, b = blockIdx.z;
    const __half* qb = qH + ((long)b * CC + h * HD) * HW;
    const __half* kb = kH + ((long)b * CC + h * HD) * HW;
    const int k0 = ch * (HW / CHG);

    float acc[2][4][4];
    #pragma unroll
    for (int mt = 0; mt < 2; mt++)
        #pragma unroll
        for (int nf = 0; nf < 4; nf++)
            #pragma unroll
            for (int r = 0; r < 4; r++) acc[mt][nf][r] = 0.f;

    const int t8 = lane >> 3, r8 = lane & 7;
    const int am = (t8 & 1) * 8 + r8, ak = (t8 >> 1) * 8;
    const int bn = (t8 >> 1) * 8 + r8, bk = (t8 & 1) * 8;

#define GR_LOAD(it, s) do {                                                        \
        uint32_t qs = sb + (s) * GR_STAGE, ks_ = qs + 32 * SK * 2;                 \
        int kb0 = (it) * 256;                                                      \
        _Pragma("unroll")                                                          \
        for (int z = 0; z < 4; z++) {                                              \
            int cidx = tid + z * 256;                                              \
            int r = cidx >> 5, c2 = cidx & 31;                                     \
            CP16(qs + r * (SK * 2) + c2 * 16,                                      \
                 __cvta_generic_to_global(qb + (long)r * HW + k0 + kb0 + c2 * 8)); \
            CP16(ks_ + r * (SK * 2) + c2 * 16,                                     \
                 __cvta_generic_to_global(kb + (long)r * HW + k0 + kb0 + c2 * 8)); \
        }                                                                          \
        asm volatile("cp.async.commit_group;");                                    \
    } while (0)

    GR_LOAD(0, 0);
    const int NIT = (HW / CHG) / 256;   // 8
    for (int it = 0; it < NIT; it++) {
        if (it + 1 < NIT) {
            GR_LOAD(it + 1, (it + 1) & 1);
            asm volatile("cp.async.wait_group 1;");
        } else {
            asm volatile("cp.async.wait_group 0;");
        }
        __syncthreads();
        uint32_t qs = sb + (it & 1) * GR_STAGE, ks_ = qs + 32 * SK * 2;
        #pragma unroll
        for (int kst = 0; kst < 2; kst++) {
            int wk = w * 32 + kst * 16;
            uint32_t a[2][4], bf[2][4];
            #pragma unroll
            for (int mt = 0; mt < 2; mt++) {
                uint32_t addr = qs + (uint32_t)(((mt * 16 + am) * SK + wk + ak) * 2);
                LDSM_X4(a[mt][0], a[mt][1], a[mt][2], a[mt][3], addr);
            }
            #pragma unroll
            for (int pp = 0; pp < 2; pp++) {
                uint32_t addr = ks_ + (uint32_t)(((pp * 16 + bn) * SK + wk + bk) * 2);
                LDSM_X4(bf[pp][0], bf[pp][1], bf[pp][2], bf[pp][3], addr);
            }
            #pragma unroll
            for (int mt = 0; mt < 2; mt++)
                #pragma unroll
                for (int nf = 0; nf < 4; nf++)
                    MMA16816(acc[mt][nf], a[mt], bf[nf >> 1][(nf & 1) * 2],
                             bf[nf >> 1][(nf & 1) * 2 + 1]);
        }
        __syncthreads();
    }
#undef GR_LOAD

    float* red = (float*)gsm;
    #pragma unroll
    for (int mt = 0; mt < 2; mt++)
        #pragma unroll
        for (int nf = 0; nf < 4; nf++)
            #pragma unroll
            for (int fr = 0; fr < 4; fr++) {
                int c = mt * 16 + (lane >> 2) + ((fr & 2) ? 8 : 0);
                int d = nf * 8 + (lane & 3) * 2 + (fr & 1);
                red[w * 1024 + c * 32 + d] = acc[mt][nf][fr];
            }
    __syncthreads();
    long base = (((long)b * NHEADS + h) * CHG + ch) * (HD * HD);
    for (int e = tid; e < 32 * HD; e += 256) {
        int c = e / HD, d = e % HD;
        if (c < HD) {
            float s = 0.f;
            #pragma unroll
            for (int ww = 0; ww < 8; ww++) s += red[ww * 1024 + c * 32 + d];
            Sp[base + c * HD + d] = s;
        }
    }
}

// ---------------- softmax + MoH = proj*blockdiag(attn) ----------------------
__global__ void attn_m(const float* __restrict__ Sp, const float* __restrict__ nqF,
                       const float* __restrict__ nkF, const float* __restrict__ temp,
                       const float* __restrict__ proj, __half* __restrict__ MoH) {
    const int h = blockIdx.x, b = blockIdx.y, tid = threadIdx.x;  // 576 threads
    __shared__ float sA[HD][HD + 1];
    __shared__ float snq[HD], snk[HD];
    const long base = ((long)b * NHEADS + h) * CHG;

    float s = 0.f;
    for (int cc = 0; cc < CHG; cc++) s += Sp[(base + cc) * (HD * HD) + tid];

    if (tid < HD) {
        snq[tid] = fmaxf(sqrtf(nqF[b * CC + h * HD + tid]), 1e-12f);
        snk[tid] = fmaxf(sqrtf(nkF[b * CC + h * HD + tid]), 1e-12f);
    }
    __syncthreads();
    {
        int c = tid / HD, d = tid % HD;
        sA[c][d] = s / (snq[c] * snk[d]) * temp[h];
    }
    __syncthreads();
    if (tid < HD) {
        float mx = -1e30f;
        for (int d = 0; d < HD; d++) mx = fmaxf(mx, sA[tid][d]);
        float sum = 0.f;
        for (int d = 0; d < HD; d++) { float e = expf(sA[tid][d] - mx); sA[tid][d] = e; sum += e; }
        float inv = 1.f / sum;
        for (int d = 0; d < HD; d++) sA[tid][d] *= inv;
    }
    __syncthreads();
    for (int l = tid; l < HD * CC; l += 576) {
        int d = l / CC, o = l % CC;
        float acc = 0.f;
        #pragma unroll
        for (int c = 0; c < HD; c++) acc += proj[o * CC + h * HD + c] * sA[c][d];
        MoH[(long)b * CC * CC + (long)o * CC + h * HD + d] = __float2half(acc);
    }
}

// ---------------- launch ----------------------------------------------------
extern "C" void kernel_launch(void* const* d_in, const int* in_sizes, int n_in,
                              void* d_out, int out_size) {
    const float* x    = (const float*)d_in[0];
    const float* y    = (const float*)d_in[1];
    const float* temp = (const float*)d_in[2];
    const float* kvw  = (const float*)d_in[3];
    const float* kvdw = (const float*)d_in[4];
    const float* qw   = (const float*)d_in[5];
    const float* qdw  = (const float*)d_in[6];
    const float* proj = (const float*)d_in[7];
    float* out = (float*)d_out;

    __half *xH, *yTpH, *kv1H, *kH, *vcmH, *vH, *qH, *w2H, *kvwH, *MoH;
    float *Sp, *nqF, *nkF;
    cudaGetSymbolAddress((void**)&xH,   g_xH);
    cudaGetSymbolAddress((void**)&yTpH, g_yTpH);
    cudaGetSymbolAddress((void**)&kv1H, g_kv1H);
    cudaGetSymbolAddress((void**)&kH,   g_kH);
    cudaGetSymbolAddress((void**)&vcmH, g_vcmH);
    cudaGetSymbolAddress((void**)&vH,   g_vH);
    cudaGetSymbolAddress((void**)&qH,   g_qH);
    cudaGetSymbolAddress((void**)&w2H,  g_w2H);
    cudaGetSymbolAddress((void**)&kvwH, g_kvwH);
    cudaGetSymbolAddress((void**)&MoH,  g_MoH);
    cudaGetSymbolAddress((void**)&Sp,   g_Sp);
    cudaGetSymbolAddress((void**)&nqF,  g_nqF);
    cudaGetSymbolAddress((void**)&nkF,  g_nkF);

    cudaFuncSetAttribute(gemm_h, cudaFuncAttributeMaxDynamicSharedMemorySize, SM_TOTAL);
    cudaFuncSetAttribute(gram_mma, cudaFuncAttributeMaxDynamicSharedMemorySize, GR_SMEM);

    // weights -> half
    conv_h<<<(2 * CC * CC + 255) / 256, 256>>>(kvw, kvwH, 2 * CC * CC);
    build_w2h<<<dim3(CC, 9), CC>>>(qdw, qw, w2H);

    // activations -> K-contiguous half layouts
    transpose_h<<<dim3(HW / 32, CC / 32, NB), dim3(32, 8)>>>(x, (long)CC * HW, xH, (long)HW * CC, 0);
    pad_zero<<<(NB * NPAD * CC + 255) / 256, 256>>>(yTpH);
    transpose_h<<<dim3(HW / 32, CC / 32, NB), dim3(32, 8)>>>(y, (long)CC * HW,
                                                             yTpH + (long)PADW * CC, (long)YSLOTS * CC, 1);

    // kv = 1x1 conv (half out)
    gemm_h<<<dim3(128, 2, NB), 256, SM_TOTAL>>>(xH, kvwH, kv1H,
        (long)HW * CC, 0L, (long)2 * CC * HW, CC, 6, 0, 1);
    // depthwise 3x3 -> kH + vcmH (ch-major)
    dwconv_h<<<NB * 2 * CC * HW / 8 / 256, 256>>>(kv1H, kvdw, kH, vcmH);
    // v -> [p][c]
    transpose_hh<<<dim3(HW / 32, CC / 32, NB), dim3(32, 8)>>>(vcmH, vH);
    // fused q conv (half out)
    gemm_h<<<dim3(IMH, 1, NB), 256, SM_TOTAL>>>(yTpH, w2H, qH,
        (long)YSLOTS * CC, 0L, (long)CC * HW, KQ, 54, 1, 1);
    // norms + gram (mma)
    norms_k<<<dim3(CC, NB, 2), 256>>>(qH, kH, nqF, nkF);
    gram_mma<<<dim3(CHG, NHEADS, NB), 256, GR_SMEM>>>(qH, kH, Sp);
    // softmax + fused proj*attn
    attn_m<<<dim3(NHEADS, NB), 576>>>(Sp, nqF, nkF, temp, proj, MoH);
    // out = (proj*attn) @ v (fp32 out)
    gemm_h<<<dim3(128, 1, NB), 256, SM_TOTAL>>>(vH, MoH, out,
        (long)HW * CC, (long)CC * CC, (long)CC * HW, CC, 6, 0, 0);
}